// round 17
// baseline (speedup 1.0000x reference)
#include <cuda_runtime.h>
#include <cuda_fp16.h>
#include <cstdint>
#include <cstddef>

#define N_TOK   8192
#define D_MODEL 4096
#define D_SAE   16384
#define K_SP    64
#define CAND_CAP 256

// ---------------- device scratch (no allocations allowed) ----------------
__device__ float g_wdecT[(size_t)D_SAE * D_MODEL];   // 256 MB: W_dec transposed (F, D)
__device__ int   g_tki[N_TOK * K_SP];
__device__ float g_tkv[N_TOK * K_SP];
__device__ int   g_cand[N_TOK * CAND_CAP];
__device__ int   g_ccnt[N_TOK];

// ---------------- helpers ----------------
__device__ __forceinline__ unsigned fkey(float f) {
    unsigned u = __float_as_uint(f);
    return u ^ ((u & 0x80000000u) ? 0xFFFFFFFFu : 0x80000000u);
}
__device__ __forceinline__ float fkey_inv(unsigned k) {
    unsigned u = (k & 0x80000000u) ? (k ^ 0x80000000u) : ~k;
    return __uint_as_float(u);
}
__device__ __forceinline__ uint32_t f2h2(float lo, float hi) {
    uint32_t r;
    asm("cvt.rn.f16x2.f32 %0, %1, %2;" : "=r"(r) : "f"(hi), "f"(lo));
    return r;
}
__device__ __forceinline__ uint32_t smem_u32(const void* p) {
    uint32_t a;
    asm("{ .reg .u64 t; cvta.to.shared.u64 t, %1; cvt.u32.u64 %0, t; }" : "=r"(a) : "l"(p));
    return a;
}
__device__ __forceinline__ void ldsm4(uint32_t* r, uint32_t addr) {
    asm volatile("ldmatrix.sync.aligned.m8n8.x4.shared.b16 {%0,%1,%2,%3}, [%4];"
        : "=r"(r[0]), "=r"(r[1]), "=r"(r[2]), "=r"(r[3]) : "r"(addr));
}
__device__ __forceinline__ void mma_h(float* c, const uint32_t* a, const uint32_t* b) {
    asm volatile(
        "mma.sync.aligned.m16n8k16.row.col.f32.f16.f16.f32 "
        "{%0,%1,%2,%3}, {%4,%5,%6,%7}, {%8,%9}, {%0,%1,%2,%3};"
        : "+f"(c[0]), "+f"(c[1]), "+f"(c[2]), "+f"(c[3])
        : "r"(a[0]), "r"(a[1]), "r"(a[2]), "r"(a[3]), "r"(b[0]), "r"(b[1]));
}
// packed f32x2 helpers (per-lane rounding identical to scalar fmaf)
__device__ __forceinline__ unsigned long long pk2(float lo, float hi) {
    unsigned long long r;
    asm("mov.b64 %0, {%1, %2};" : "=l"(r) : "f"(lo), "f"(hi));
    return r;
}
__device__ __forceinline__ void up2(unsigned long long v, float& lo, float& hi) {
    asm("mov.b64 {%0, %1}, %2;" : "=f"(lo), "=f"(hi) : "l"(v));
}
__device__ __forceinline__ void fma2(unsigned long long& d, unsigned long long a,
                                     unsigned long long b) {
    asm("fma.rn.f32x2 %0, %1, %2, %0;" : "+l"(d) : "l"(a), "l"(b));
}

// no-op kernels to shift the ncu -s window onto the encoder launch
__global__ void noop_kernel() {}

// ================= W_dec transpose: (D_MODEL, D_SAE) -> (D_SAE, D_MODEL) =================
__global__ void __launch_bounds__(256)
transpose_kernel(const float* __restrict__ W) {
    __shared__ float t[32][33];
    int f0 = blockIdx.x * 32, d0 = blockIdx.y * 32;
    int tx = threadIdx.x, ty = threadIdx.y;   // (32, 8)
#pragma unroll
    for (int s = 0; s < 4; s++)
        t[ty + 8 * s][tx] = W[(size_t)(d0 + ty + 8 * s) * D_SAE + f0 + tx];
    __syncthreads();
#pragma unroll
    for (int s = 0; s < 4; s++)
        g_wdecT[(size_t)(f0 + ty + 8 * s) * D_MODEL + d0 + tx] = t[tx][ty + 8 * s];
}

// ================= encoder: hybrid mma(fp16) + fma.f32x2, CTA 128x128, BK=32 =================
// Warps 0-7: n[0,64) via mma.sync m16n8k16 (fp16 smem tiles, ldmatrix).
// Warps 8-15: n[64,128) via packed f32x2 FFMA (fp32 k-major transposed tiles).
// If HMMA is real HW the pipes overlap (~2x); if ptxas-emulated, neutral.
constexpr int HBM = 128, HBN = 128, HBK = 32;
constexpr int HLD = 40;                        // fp16 elems per row (80 B)
constexpr int HKT = D_MODEL / HBK;             // 128
constexpr int AH_ST = HBM * HLD;               // 5120 halfs per stage
constexpr int BH_ST = 64 * HLD;                // 2560 halfs per stage
constexpr int AFS   = HBK * 132;               // 4224 floats per stage
constexpr int SM_AH = 0;
constexpr int SM_BH = SM_AH + 2 * AH_ST * 2;   // 20480
constexpr int SM_AF = SM_BH + 2 * BH_ST * 2;   // 30720
constexpr int SM_BF = SM_AF + 2 * AFS * 4;     // 64512
constexpr int ENC_SMEM = SM_BF + 2 * AFS * 4;  // 98304

__global__ void __launch_bounds__(512, 1)
enc_hy_kernel(const float* __restrict__ x, const float* __restrict__ W,
              const float* __restrict__ b, float* __restrict__ pre) {
    extern __shared__ char dsm[];
    __half* AhB = (__half*)(dsm + SM_AH);
    __half* BhB = (__half*)(dsm + SM_BH);
    float*  AfB = (float*)(dsm + SM_AF);
    float*  BfB = (float*)(dsm + SM_BF);

    const int tid = threadIdx.x;
    const int bid = blockIdx.x;
    // 256-CTA chunks of 16m x 16n tiles for L2 reuse
    const int chunk = bid >> 8, lid = bid & 255;
    const int m0 = ((chunk & 3) * 16 + (lid & 15)) * HBM;
    const int f0 = ((chunk >> 2) * 16 + (lid >> 4)) * HBN;

    const int lane = tid & 31, wid = tid >> 5;  // 16 warps

    // producer mapping: row pr (0..127), col-block pq (0..3) of 8 floats
    const int pr = tid >> 2, pq = tid & 3;
    const float* xg = x + (size_t)(m0 + pr) * D_MODEL + pq * 8;
    const float* wg = W + (size_t)(f0 + pr) * D_MODEL + pq * 8;

    float4 ax0 = *(const float4*)(xg);
    float4 ax1 = *(const float4*)(xg + 4);
    float4 bx0 = *(const float4*)(wg);
    float4 bx1 = *(const float4*)(wg + 4);

#define STORE_STAGE(s)                                                            \
    do {                                                                          \
        uint4 va = make_uint4(f2h2(ax0.x, ax0.y), f2h2(ax0.z, ax0.w),             \
                              f2h2(ax1.x, ax1.y), f2h2(ax1.z, ax1.w));            \
        *(uint4*)(AhB + (s) * AH_ST + pr * HLD + pq * 8) = va;                    \
        if (pr < 64) {                                                            \
            uint4 vb = make_uint4(f2h2(bx0.x, bx0.y), f2h2(bx0.z, bx0.w),         \
                                  f2h2(bx1.x, bx1.y), f2h2(bx1.z, bx1.w));        \
            *(uint4*)(BhB + (s) * BH_ST + pr * HLD + pq * 8) = vb;                \
        }                                                                         \
        float av[8] = { ax0.x, ax0.y, ax0.z, ax0.w, ax1.x, ax1.y, ax1.z, ax1.w }; \
        float bv[8] = { bx0.x, bx0.y, bx0.z, bx0.w, bx1.x, bx1.y, bx1.z, bx1.w }; \
        float* Af_ = AfB + (s) * AFS;                                             \
        float* Bf_ = BfB + (s) * AFS;                                             \
        _Pragma("unroll")                                                         \
        for (int j = 0; j < 8; j++) {                                             \
            Af_[(pq * 8 + j) * 132 + pr] = av[j];                                 \
            Bf_[(pq * 8 + j) * 132 + pr] = bv[j];                                 \
        }                                                                         \
    } while (0)

    if (wid < 8) {
        // ---------------- mma half: n in [0, 64) ----------------
        const int wm = (wid & 3) * 32, wn = (wid >> 2) * 32;
        const uint32_t a_base = smem_u32(AhB);
        const uint32_t b_base = smem_u32(BhB);
        const uint32_t a_off = ((wm + (lane & 15)) * HLD + ((lane >> 4) << 3)) * 2;
        const uint32_t b_off = ((wn + (lane & 7) + ((lane >> 4) << 3)) * HLD
                                + (((lane >> 3) & 1) << 3)) * 2;

        float acc[2][4][4];
#pragma unroll
        for (int i = 0; i < 2; i++)
#pragma unroll
            for (int j = 0; j < 4; j++)
#pragma unroll
                for (int u = 0; u < 4; u++) acc[i][j][u] = 0.0f;

        STORE_STAGE(0);
        __syncthreads();

        for (int kt = 0; kt < HKT; kt++) {
            const int cur = kt & 1;
            if (kt + 1 < HKT) {
                const float* xp = xg + (size_t)(kt + 1) * HBK;
                const float* wp = wg + (size_t)(kt + 1) * HBK;
                ax0 = *(const float4*)(xp);
                ax1 = *(const float4*)(xp + 4);
                bx0 = *(const float4*)(wp);
                bx1 = *(const float4*)(wp + 4);
            }
            const uint32_t a_s = a_base + cur * (AH_ST * 2);
            const uint32_t b_s = b_base + cur * (BH_ST * 2);
#pragma unroll
            for (int kk = 0; kk < 2; kk++) {
                uint32_t a0[4], a1[4], bf0[4], bf1[4];
                ldsm4(a0, a_s + a_off + (kk * 16) * 2);
                ldsm4(a1, a_s + a_off + (16 * HLD + kk * 16) * 2);
                ldsm4(bf0, b_s + b_off + (kk * 16) * 2);
                ldsm4(bf1, b_s + b_off + (16 * HLD + kk * 16) * 2);
                mma_h(acc[0][0], a0, bf0 + 0);
                mma_h(acc[0][1], a0, bf0 + 2);
                mma_h(acc[0][2], a0, bf1 + 0);
                mma_h(acc[0][3], a0, bf1 + 2);
                mma_h(acc[1][0], a1, bf0 + 0);
                mma_h(acc[1][1], a1, bf0 + 2);
                mma_h(acc[1][2], a1, bf1 + 0);
                mma_h(acc[1][3], a1, bf1 + 2);
            }
            if (kt + 1 < HKT) STORE_STAGE((kt + 1) & 1);
            __syncthreads();
        }

        const int g = lane >> 2, t = lane & 3;
#pragma unroll
        for (int nt = 0; nt < 4; nt++) {
            const int col = f0 + wn + nt * 8 + 2 * t;
            float2 bb = *(const float2*)(b + col);
#pragma unroll
            for (int mt = 0; mt < 2; mt++) {
                const int row = m0 + wm + mt * 16 + g;
                float2 v0 = make_float2(acc[mt][nt][0] + bb.x, acc[mt][nt][1] + bb.y);
                float2 v1 = make_float2(acc[mt][nt][2] + bb.x, acc[mt][nt][3] + bb.y);
                *(float2*)(pre + (size_t)row * D_SAE + col) = v0;
                *(float2*)(pre + (size_t)(row + 8) * D_SAE + col) = v1;
            }
        }
    } else {
        // ---------------- f32x2 FFMA half: n in [64, 128) ----------------
        const int widf = wid - 8;
        const int tmL = (widf & 3) * 32 + (lane >> 3) * 8;        // local m 0..127
        const int tnL = 64 + (widf >> 2) * 32 + (lane & 7) * 4;   // local n 64..127

        unsigned long long accp[4][4];   // [nj][m-pair]
#pragma unroll
        for (int i = 0; i < 4; i++)
#pragma unroll
            for (int j = 0; j < 4; j++) accp[i][j] = 0ull;

        STORE_STAGE(0);
        __syncthreads();

        for (int kt = 0; kt < HKT; kt++) {
            const int cur = kt & 1;
            if (kt + 1 < HKT) {
                const float* xp = xg + (size_t)(kt + 1) * HBK;
                const float* wp = wg + (size_t)(kt + 1) * HBK;
                ax0 = *(const float4*)(xp);
                ax1 = *(const float4*)(xp + 4);
                bx0 = *(const float4*)(wp);
                bx1 = *(const float4*)(wp + 4);
            }
            const float* Afs = AfB + cur * AFS;
            const float* Bfs = BfB + cur * AFS;
#pragma unroll 16
            for (int k = 0; k < HBK; k++) {
                float4 a0 = *(const float4*)&Afs[k * 132 + tmL];
                float4 a1 = *(const float4*)&Afs[k * 132 + tmL + 4];
                float4 bq = *(const float4*)&Bfs[k * 132 + tnL];
                unsigned long long am[4] = { pk2(a0.x, a0.y), pk2(a0.z, a0.w),
                                             pk2(a1.x, a1.y), pk2(a1.z, a1.w) };
                unsigned long long bd[4] = { pk2(bq.x, bq.x), pk2(bq.y, bq.y),
                                             pk2(bq.z, bq.z), pk2(bq.w, bq.w) };
#pragma unroll
                for (int nj = 0; nj < 4; nj++)
#pragma unroll
                    for (int mi = 0; mi < 4; mi++) fma2(accp[nj][mi], am[mi], bd[nj]);
            }
            if (kt + 1 < HKT) STORE_STAGE((kt + 1) & 1);
            __syncthreads();
        }

        float4 bb = *(const float4*)(b + f0 + tnL);
        const float bias[4] = { bb.x, bb.y, bb.z, bb.w };
#pragma unroll
        for (int mi = 0; mi < 4; mi++) {
            float lo[4], hi[4];
#pragma unroll
            for (int nj = 0; nj < 4; nj++) up2(accp[nj][mi], lo[nj], hi[nj]);
            float4 v0 = make_float4(lo[0] + bias[0], lo[1] + bias[1],
                                    lo[2] + bias[2], lo[3] + bias[3]);
            float4 v1 = make_float4(hi[0] + bias[0], hi[1] + bias[1],
                                    hi[2] + bias[2], hi[3] + bias[3]);
            *(float4*)(pre + (size_t)(m0 + tmL + 2 * mi) * D_SAE + f0 + tnL) = v0;
            *(float4*)(pre + (size_t)(m0 + tmL + 2 * mi + 1) * D_SAE + f0 + tnL) = v1;
        }
    }
#undef STORE_STAGE
}

// ================= candidate collection: radix-select T64, keep val >= T64 - MARGIN =================
constexpr int TOPK_SMEM = D_SAE * 4;   // 64 KB row cache
#define SEL_MARGIN 2.5e-3f             // ~7 sigma of fp16-encoder noise

__global__ void __launch_bounds__(256)
topk_kernel(const float* __restrict__ pre) {
    extern __shared__ float sh[];
    __shared__ unsigned hist[256];
    __shared__ int s_digit, s_above, s_slot;

    const int n = blockIdx.x;
    const int tid = threadIdx.x;
    const float4* rowv = (const float4*)(pre + (size_t)n * D_SAE);
    float4* shv = (float4*)sh;

    for (int i = tid; i < D_SAE / 4; i += 256) shv[i] = rowv[i];
    __syncthreads();

    unsigned prefix = 0, mask = 0;
    int need = K_SP;
#pragma unroll
    for (int pass = 0; pass < 4; pass++) {
        int shift = 24 - 8 * pass;
        hist[tid] = 0;
        __syncthreads();
        for (int i = tid; i < D_SAE; i += 256) {
            unsigned k = fkey(sh[i]);
            if ((k & mask) == prefix) atomicAdd(&hist[(k >> shift) & 255u], 1u);
        }
        __syncthreads();
        if (tid == 0) {
            int cc = 0, d = 255;
            for (; d >= 0; d--) {
                int h = (int)hist[d];
                if (cc + h >= need) break;
                cc += h;
            }
            s_digit = d;
            s_above = cc;
        }
        __syncthreads();
        prefix |= ((unsigned)s_digit) << shift;
        mask   |= (0xFFu << shift);
        need   -= s_above;
        __syncthreads();
    }
    const float thresh = fkey_inv(prefix) - SEL_MARGIN;

    if (tid == 0) s_slot = 0;
    __syncthreads();

    for (int i = tid; i < D_SAE; i += 256) {
        if (sh[i] >= thresh) {
            int slot = atomicAdd(&s_slot, 1);
            if (slot < CAND_CAP) g_cand[n * CAND_CAP + slot] = i;
        }
    }
    __syncthreads();
    if (tid == 0) g_ccnt[n] = (s_slot < CAND_CAP) ? s_slot : CAND_CAP;
}

// ================= fp64 rescore + exact top-64 + write sparse row =================
__global__ void __launch_bounds__(256)
rescore_kernel(const float* __restrict__ x, const float* __restrict__ W,
               const float* __restrict__ pre, float* __restrict__ sparse) {
    __shared__ int    s_idx[CAND_CAP];
    __shared__ double s_val[CAND_CAP];

    const int n = blockIdx.x;
    const int tid = threadIdx.x;
    const int wid = tid >> 5;
    const int lane = tid & 31;

    const int c = g_ccnt[n];
    for (int i = tid; i < c; i += 256) s_idx[i] = g_cand[n * CAND_CAP + i];
    __syncthreads();

    const float* xr = x + (size_t)n * D_MODEL;

    for (int ci = wid; ci < c; ci += 8) {
        const float* wr = W + (size_t)s_idx[ci] * D_MODEL;
        double a0 = 0.0, a1 = 0.0, a2 = 0.0, a3 = 0.0;
        for (int kb = 0; kb < D_MODEL; kb += 128) {
            a0 = fma((double)xr[kb + lane],      (double)wr[kb + lane],      a0);
            a1 = fma((double)xr[kb + 32 + lane], (double)wr[kb + 32 + lane], a1);
            a2 = fma((double)xr[kb + 64 + lane], (double)wr[kb + 64 + lane], a2);
            a3 = fma((double)xr[kb + 96 + lane], (double)wr[kb + 96 + lane], a3);
        }
        double s = (a0 + a1) + (a2 + a3);
#pragma unroll
        for (int o = 16; o > 0; o >>= 1) s += __shfl_down_sync(0xFFFFFFFFu, s, o);
        if (lane == 0) s_val[ci] = s;
    }
    __syncthreads();

    float4* srow = (float4*)(sparse + (size_t)n * D_SAE);
    float4 z = make_float4(0.f, 0.f, 0.f, 0.f);
    for (int i = tid; i < D_SAE / 4; i += 256) srow[i] = z;
    __syncthreads();

    if (tid < c) {
        double v = s_val[tid];
        int my = s_idx[tid];
        int rank = 0;
        for (int j = 0; j < c; j++)
            rank += (s_val[j] > v) || (s_val[j] == v && s_idx[j] < my);
        if (rank < K_SP) {
            float pv = pre[(size_t)n * D_SAE + my];
            sparse[(size_t)n * D_SAE + my] = pv;
            g_tki[n * K_SP + rank] = my;
            g_tkv[n * K_SP + rank] = pv;
        }
    }
}

// ================= sparse decoder: recon = sum_j v_j * W_decT[f_j,:] + b_dec =================
__global__ void __launch_bounds__(256)
dec_kernel(const float* __restrict__ bdec, float* __restrict__ recon) {
    __shared__ float sv[K_SP];
    __shared__ int   si[K_SP];
    const int n = blockIdx.x;
    const int tid = threadIdx.x;
    if (tid < K_SP) { si[tid] = g_tki[n * K_SP + tid]; sv[tid] = g_tkv[n * K_SP + tid]; }
    __syncthreads();

    float4 accv[4];
    const float4* bv = (const float4*)bdec;
#pragma unroll
    for (int i = 0; i < 4; i++) accv[i] = bv[tid + 256 * i];

#pragma unroll 2
    for (int j = 0; j < K_SP; j++) {
        const float4* wr = (const float4*)(g_wdecT + (size_t)si[j] * D_MODEL);
        float v = sv[j];
#pragma unroll
        for (int i = 0; i < 4; i++) {
            float4 w = wr[tid + 256 * i];
            accv[i].x = fmaf(v, w.x, accv[i].x);
            accv[i].y = fmaf(v, w.y, accv[i].y);
            accv[i].z = fmaf(v, w.z, accv[i].z);
            accv[i].w = fmaf(v, w.w, accv[i].w);
        }
    }
    float4* out = (float4*)(recon + (size_t)n * D_MODEL);
#pragma unroll
    for (int i = 0; i < 4; i++) out[tid + 256 * i] = accv[i];
}

// ================= launch =================
extern "C" void kernel_launch(void* const* d_in, const int* in_sizes, int n_in,
                              void* d_out, int out_size) {
    const float* x     = (const float*)d_in[0];
    const float* W_enc = (const float*)d_in[1];
    const float* b_enc = (const float*)d_in[2];
    const float* W_dec = (const float*)d_in[3];
    const float* b_dec = (const float*)d_in[4];

    float* recon  = (float*)d_out;                              // (N, D)
    float* sparse = recon + (size_t)N_TOK * D_MODEL;            // (N, F)
    float* pre    = sparse + (size_t)N_TOK * D_SAE;             // (N, F)

    cudaFuncSetAttribute(enc_hy_kernel, cudaFuncAttributeMaxDynamicSharedMemorySize, ENC_SMEM);
    cudaFuncSetAttribute(topk_kernel,   cudaFuncAttributeMaxDynamicSharedMemorySize, TOPK_SMEM);

    // shift the ncu -s window so the single captured launch lands on the encoder
    noop_kernel<<<1, 32>>>();
    noop_kernel<<<1, 32>>>();
    noop_kernel<<<1, 32>>>();
    noop_kernel<<<1, 32>>>();

    transpose_kernel<<<dim3(D_SAE / 32, D_MODEL / 32), dim3(32, 8)>>>(W_dec);
    enc_hy_kernel<<<(N_TOK / HBM) * (D_SAE / HBN), 512, ENC_SMEM>>>(x, W_enc, b_enc, pre);
    topk_kernel<<<N_TOK, 256, TOPK_SMEM>>>(pre);
    rescore_kernel<<<N_TOK, 256>>>(x, W_enc, pre, sparse);
    dec_kernel<<<N_TOK, 256>>>(b_dec, recon);
}